// round 8
// baseline (speedup 1.0000x reference)
#include <cuda_runtime.h>

#define DIMC 192
#define RR   48
#define BB   4
#define HH   256
#define WW   256
#define HW   (HH * WW)
#define EPSV 1e-5f
#define TROWS 16
#define SPITCH 260   // smem row pitch in floats (256 + 4 pad)

__device__ float g_part[2 * BB * DIMC];      // partial pool sums
__device__ float g_wt[BB * DIMC * 4];        // 4 live taps per (b,c)

// ---------------------------------------------------------------------------
// Kernel 1: partial global average pool. Two blocks (512 thr) per channel.
// ---------------------------------------------------------------------------
__global__ void __launch_bounds__(512) pool_kernel(const float* __restrict__ x) {
    const int bc   = blockIdx.x >> 1;
    const int half = blockIdx.x & 1;
    const float4* p = (const float4*)(x + (size_t)bc * HW + (size_t)half * (HW / 2));
    const int n4 = HW / 8;                      // 8192 float4 per half
    float s0 = 0.f, s1 = 0.f;
    for (int i = threadIdx.x; i < n4; i += 1024) {
        float4 a = p[i];
        float4 b = p[i + 512];
        s0 += (a.x + a.y) + (a.z + a.w);
        s1 += (b.x + b.y) + (b.z + b.w);
    }
    float s = s0 + s1;
    #pragma unroll
    for (int o = 16; o > 0; o >>= 1) s += __shfl_xor_sync(0xffffffffu, s, o);
    __shared__ float sm[16];
    if ((threadIdx.x & 31) == 0) sm[threadIdx.x >> 5] = s;
    __syncthreads();
    if (threadIdx.x == 0) {
        float t = 0.f;
        #pragma unroll
        for (int i = 0; i < 16; i++) t += sm[i];
        g_part[blockIdx.x] = t;
    }
}

// ---------------------------------------------------------------------------
// Kernel 2: weight-gen MLP (tiny, single block).
// ---------------------------------------------------------------------------
__global__ void __launch_bounds__(256) wgen_kernel(
    const float* __restrict__ w1,
    const float* __restrict__ gamma, const float* __restrict__ beta,
    const float* __restrict__ rmean, const float* __restrict__ rvar,
    const float* __restrict__ w2,   const float* __restrict__ b2)
{
    __shared__ float s_pool[BB * DIMC];
    __shared__ float s_t[BB * RR];
    const int tid = threadIdx.x;

    for (int i = tid; i < BB * DIMC; i += 256)
        s_pool[i] = (g_part[2 * i] + g_part[2 * i + 1]) * (1.0f / (float)HW);
    __syncthreads();

    if (tid < BB * RR) {
        const int b = tid / RR;
        const int j = tid % RR;
        const float* pl = s_pool + b * DIMC;
        const float* wr = w1 + j * DIMC;
        float acc = 0.f;
        #pragma unroll 4
        for (int c = 0; c < DIMC; c++) acc = fmaf(pl[c], wr[c], acc);
        float v = gamma[j] * (acc - rmean[j]) * rsqrtf(rvar[j] + EPSV) + beta[j];
        s_t[tid] = fmaxf(v, 0.f);
    }
    __syncthreads();

    const int NKEPT = BB * DIMC * 4;            // 3072
    for (int idx = tid; idx < NKEPT; idx += 256) {
        const int b   = idx / (DIMC * 4);
        const int rem = idx % (DIMC * 4);
        const int c   = rem >> 2;
        const int tap = rem & 3;
        const int o   = c * 9 + tap;
        const float* tv = s_t + b * RR;
        const float* wr = w2 + o * RR;
        float acc = b2[o];
        #pragma unroll
        for (int j = 0; j < RR; j++) acc = fmaf(tv[j], wr[j], acc);
        g_wt[idx] = acc;
    }
}

// ---------------------------------------------------------------------------
// Kernel 3: 4-tap masked depthwise stencil + bias via smem row tile.
//   out[y][x] = w0*in[y-1][x-1] + w1*in[y-1][x] + w2*in[y-1][x+1]
//             + w3*in[y][x-1]   + bias[c]
// Block: 256 threads; tile: 16 rows x 256 cols (+1 halo row above).
// grid = (16, 768)
// ---------------------------------------------------------------------------
__global__ void __launch_bounds__(256) conv_kernel(
    const float* __restrict__ x, const float* __restrict__ bias,
    float* __restrict__ out)
{
    __shared__ float s[(TROWS + 1) * SPITCH];

    const int bc  = blockIdx.y;
    const int c   = bc % DIMC;
    const int r0  = blockIdx.x * TROWS;
    const int tid = threadIdx.x;

    const float w0 = g_wt[bc * 4 + 0];
    const float w1 = g_wt[bc * 4 + 1];
    const float w2 = g_wt[bc * 4 + 2];
    const float w3 = g_wt[bc * 4 + 3];
    const float bv = bias[c];

    const float* in = x + (size_t)bc * HW;

    // Load 17 rows (r0-1 .. r0+15), float4-coalesced.
    const int NL = (TROWS + 1) * (WW / 4);      // 1088 float4
    #pragma unroll 5
    for (int L = tid; L < NL; L += 256) {
        const int srow  = L >> 6;               // 0..16
        const int scol4 = (L & 63) << 2;
        const int grow  = r0 - 1 + srow;
        float4 v = make_float4(0.f, 0.f, 0.f, 0.f);
        if (grow >= 0)
            v = *(const float4*)(in + (size_t)grow * WW + scol4);
        *(float4*)&s[srow * SPITCH + scol4] = v;
    }
    __syncthreads();

    const int col4 = tid & 63;
    const int x4   = col4 << 2;
    const int rowb = tid >> 6;                  // 0..3
    float* ot = out + (size_t)bc * HW;

    #pragma unroll
    for (int i = 0; i < 4; i++) {
        const int r = rowb + i * 4;             // 0..15: output row r0+r
        const float* pr_ = &s[r * SPITCH];      // prev row (global r0+r-1)
        const float* cu_ = &s[(r + 1) * SPITCH];

        float4 pv = *(const float4*)&pr_[x4];
        float  pl = (x4 > 0)       ? pr_[x4 - 1] : 0.f;
        float  pq = (x4 + 4 < WW)  ? pr_[x4 + 4] : 0.f;
        float4 cv = *(const float4*)&cu_[x4];
        float  cl = (x4 > 0)       ? cu_[x4 - 1] : 0.f;

        float4 o;
        o.x = fmaf(w0, pl,   fmaf(w1, pv.x, fmaf(w2, pv.y, fmaf(w3, cl,   bv))));
        o.y = fmaf(w0, pv.x, fmaf(w1, pv.y, fmaf(w2, pv.z, fmaf(w3, cv.x, bv))));
        o.z = fmaf(w0, pv.y, fmaf(w1, pv.z, fmaf(w2, pv.w, fmaf(w3, cv.y, bv))));
        o.w = fmaf(w0, pv.z, fmaf(w1, pv.w, fmaf(w2, pq,   fmaf(w3, cv.z, bv))));

        *(float4*)(ot + (size_t)(r0 + r) * WW + x4) = o;
    }
}

// ---------------------------------------------------------------------------
extern "C" void kernel_launch(void* const* d_in, const int* in_sizes, int n_in,
                              void* d_out, int out_size)
{
    const float* x     = (const float*)d_in[0];
    const float* w1    = (const float*)d_in[1];
    const float* gamma = (const float*)d_in[2];
    const float* beta  = (const float*)d_in[3];
    const float* rmean = (const float*)d_in[4];
    const float* rvar  = (const float*)d_in[5];
    const float* w2    = (const float*)d_in[6];
    const float* b2    = (const float*)d_in[7];
    const float* bias  = (const float*)d_in[8];
    float* out = (float*)d_out;

    pool_kernel<<<2 * BB * DIMC, 512>>>(x);
    wgen_kernel<<<1, 256>>>(w1, gamma, beta, rmean, rvar, w2, b2);
    dim3 grd(HH / TROWS, BB * DIMC);
    conv_kernel<<<grd, 256>>>(x, bias, out);
}

// round 9
// speedup vs baseline: 1.5500x; 1.5500x over previous
#include <cuda_runtime.h>

#define DIMC 192
#define RR   48
#define BB   4
#define HH   256
#define WW   256
#define HW   (HH * WW)
#define EPSV 1e-5f
#define TROWS 16
#define SPITCH 260   // smem row pitch in floats (256 + 4 pad)

__device__ float g_part[2 * BB * DIMC];      // partial pool sums
__device__ float g_t[BB * RR];               // hidden activations
__device__ float g_wt[BB * DIMC * 4];        // 4 live taps per (b,c)

// ---------------------------------------------------------------------------
// Kernel 1: partial global average pool. Two blocks (512 thr) per channel.
// ---------------------------------------------------------------------------
__global__ void __launch_bounds__(512) pool_kernel(const float* __restrict__ x) {
    const int bc   = blockIdx.x >> 1;
    const int half = blockIdx.x & 1;
    const float4* p = (const float4*)(x + (size_t)bc * HW + (size_t)half * (HW / 2));
    const int n4 = HW / 8;
    float s0 = 0.f, s1 = 0.f;
    for (int i = threadIdx.x; i < n4; i += 1024) {
        float4 a = p[i];
        float4 b = p[i + 512];
        s0 += (a.x + a.y) + (a.z + a.w);
        s1 += (b.x + b.y) + (b.z + b.w);
    }
    float s = s0 + s1;
    #pragma unroll
    for (int o = 16; o > 0; o >>= 1) s += __shfl_xor_sync(0xffffffffu, s, o);
    __shared__ float sm[16];
    if ((threadIdx.x & 31) == 0) sm[threadIdx.x >> 5] = s;
    __syncthreads();
    if (threadIdx.x == 0) {
        float t = 0.f;
        #pragma unroll
        for (int i = 0; i < 16; i++) t += sm[i];
        g_part[blockIdx.x] = t;
    }
}

// ---------------------------------------------------------------------------
// Kernel 2a: t = relu(BN(pooled @ w1^T)). Warp per (j,b). 192 warps = 24 blocks.
// ---------------------------------------------------------------------------
__global__ void __launch_bounds__(256) wgen_a_kernel(
    const float* __restrict__ w1,
    const float* __restrict__ gamma, const float* __restrict__ beta,
    const float* __restrict__ rmean, const float* __restrict__ rvar)
{
    const int gw   = blockIdx.x * 8 + (threadIdx.x >> 5);   // 0..191
    const int lane = threadIdx.x & 31;
    const int j    = gw % RR;
    const int b    = gw / RR;

    float acc = 0.f;
    #pragma unroll
    for (int k = 0; k < DIMC / 32; k++) {
        const int c = lane + k * 32;
        const float pooled = (g_part[2 * (b * DIMC + c)] + g_part[2 * (b * DIMC + c) + 1])
                             * (1.0f / (float)HW);
        acc = fmaf(w1[j * DIMC + c], pooled, acc);
    }
    #pragma unroll
    for (int o = 16; o > 0; o >>= 1) acc += __shfl_xor_sync(0xffffffffu, acc, o);
    if (lane == 0) {
        float v = gamma[j] * (acc - rmean[j]) * rsqrtf(rvar[j] + EPSV) + beta[j];
        g_t[b * RR + j] = fmaxf(v, 0.f);
    }
}

// ---------------------------------------------------------------------------
// Kernel 2b: taps = t @ w2^T + b2 (masked: 4 taps per channel).
// Warp per output. 3072 outputs = 384 blocks x 8 warps.
// ---------------------------------------------------------------------------
__global__ void __launch_bounds__(256) wgen_b_kernel(
    const float* __restrict__ w2, const float* __restrict__ b2)
{
    const int idx  = blockIdx.x * 8 + (threadIdx.x >> 5);   // 0..3071
    const int lane = threadIdx.x & 31;
    const int b    = idx / (DIMC * 4);
    const int rem  = idx % (DIMC * 4);
    const int c    = rem >> 2;
    const int tap  = rem & 3;
    const int o    = c * 9 + tap;

    const float* tv = g_t + b * RR;
    const float* wr = w2 + o * RR;
    float acc = tv[lane] * wr[lane];
    if (lane < RR - 32) acc = fmaf(tv[lane + 32], wr[lane + 32], acc);
    #pragma unroll
    for (int off = 16; off > 0; off >>= 1) acc += __shfl_xor_sync(0xffffffffu, acc, off);
    if (lane == 0) g_wt[(b * DIMC + c) * 4 + tap] = acc + b2[o];
}

// ---------------------------------------------------------------------------
// Kernel 3: 4-tap masked depthwise stencil + bias via smem row tile.
// Streaming hints: __ldcs on x, __stcs on out.
// ---------------------------------------------------------------------------
__global__ void __launch_bounds__(256) conv_kernel(
    const float* __restrict__ x, const float* __restrict__ bias,
    float* __restrict__ out)
{
    __shared__ float s[(TROWS + 1) * SPITCH];

    const int bc  = blockIdx.y;
    const int c   = bc % DIMC;
    const int r0  = blockIdx.x * TROWS;
    const int tid = threadIdx.x;

    const float w0 = g_wt[bc * 4 + 0];
    const float w1 = g_wt[bc * 4 + 1];
    const float w2 = g_wt[bc * 4 + 2];
    const float w3 = g_wt[bc * 4 + 3];
    const float bv = bias[c];

    const float* in = x + (size_t)bc * HW;

    const int NL = (TROWS + 1) * (WW / 4);      // 1088 float4
    #pragma unroll 5
    for (int L = tid; L < NL; L += 256) {
        const int srow  = L >> 6;
        const int scol4 = (L & 63) << 2;
        const int grow  = r0 - 1 + srow;
        float4 v = make_float4(0.f, 0.f, 0.f, 0.f);
        if (grow >= 0)
            v = __ldcs((const float4*)(in + (size_t)grow * WW + scol4));
        *(float4*)&s[srow * SPITCH + scol4] = v;
    }
    __syncthreads();

    const int col4 = tid & 63;
    const int x4   = col4 << 2;
    const int rowb = tid >> 6;
    float* ot = out + (size_t)bc * HW;

    #pragma unroll
    for (int i = 0; i < 4; i++) {
        const int r = rowb + i * 4;
        const float* pr_ = &s[r * SPITCH];
        const float* cu_ = &s[(r + 1) * SPITCH];

        float4 pv = *(const float4*)&pr_[x4];
        float  pl = (x4 > 0)       ? pr_[x4 - 1] : 0.f;
        float  pq = (x4 + 4 < WW)  ? pr_[x4 + 4] : 0.f;
        float4 cv = *(const float4*)&cu_[x4];
        float  cl = (x4 > 0)       ? cu_[x4 - 1] : 0.f;

        float4 o;
        o.x = fmaf(w0, pl,   fmaf(w1, pv.x, fmaf(w2, pv.y, fmaf(w3, cl,   bv))));
        o.y = fmaf(w0, pv.x, fmaf(w1, pv.y, fmaf(w2, pv.z, fmaf(w3, cv.x, bv))));
        o.z = fmaf(w0, pv.y, fmaf(w1, pv.z, fmaf(w2, pv.w, fmaf(w3, cv.y, bv))));
        o.w = fmaf(w0, pv.z, fmaf(w1, pv.w, fmaf(w2, pq,   fmaf(w3, cv.z, bv))));

        __stcs((float4*)(ot + (size_t)(r0 + r) * WW + x4), o);
    }
}

// ---------------------------------------------------------------------------
extern "C" void kernel_launch(void* const* d_in, const int* in_sizes, int n_in,
                              void* d_out, int out_size)
{
    const float* x     = (const float*)d_in[0];
    const float* w1    = (const float*)d_in[1];
    const float* gamma = (const float*)d_in[2];
    const float* beta  = (const float*)d_in[3];
    const float* rmean = (const float*)d_in[4];
    const float* rvar  = (const float*)d_in[5];
    const float* w2    = (const float*)d_in[6];
    const float* b2    = (const float*)d_in[7];
    const float* bias  = (const float*)d_in[8];
    float* out = (float*)d_out;

    pool_kernel<<<2 * BB * DIMC, 512>>>(x);
    wgen_a_kernel<<<24, 256>>>(w1, gamma, beta, rmean, rvar);
    wgen_b_kernel<<<384, 256>>>(w2, b2);
    dim3 grd(HH / TROWS, BB * DIMC);
    conv_kernel<<<grd, 256>>>(x, bias, out);
}